// round 16
// baseline (speedup 1.0000x reference)
#include <cuda_runtime.h>
#include <cuda_bf16.h>
#include <mma.h>
#include <math.h>
#include <stdint.h>

using namespace nvcuda;

// ---------------------------------------------------------------------------
// CrossMambaBlock — split-bf16 tensor-core GEMMs + fp32 scan
// B=2, D_MODEL=128, H=W=96 (L=9216), D_INNER=256, D_STATE=16, D_CONV=4, DT_RANK=8
// ---------------------------------------------------------------------------

#define B_    2
#define CM    128
#define HH    96
#define WW    96
#define LL    (HH*WW)        // 9216
#define DI    256
#define DS    16
#define DR    8
#define NSEG  32
#define SEG   (LL/NSEG)      // 288
#define XDP   64             // padded xdbl channel count (real = 40)

typedef __nv_bfloat16 bf16;

// ---- fp32 scratch ----
__device__ __align__(16) float g_qpre [B_*CM*LL];
__device__ __align__(16) float g_kvpre[B_*2*CM*LL];
__device__ __align__(16) float g_xmpre[B_*DI*LL];
__device__ __align__(16) float g_z    [B_*DI*LL];
__device__ __align__(16) float g_xm   [B_*DI*LL];
__device__ __align__(16) float g_xdbl [B_*XDP*LL];
__device__ __align__(16) float g_dt   [B_*DI*LL];
__device__ __align__(16) float g_Bm   [B_*LL*DS];
__device__ __align__(16) float g_Cm   [B_*LL*DS];
__device__ __align__(16) float g_hend [B_*DI*NSEG*DS];
__device__ __align__(16) float g_h0   [B_*DI*NSEG*DS];
__device__ __align__(16) float g_sumdt[B_*DI*NSEG];
__device__ __align__(16) float g_Wf   [CM*(DI+CM)];

// ---- bf16 hi/lo activation scratch ----
__device__ __align__(16) bf16 g_xh [B_*CM*LL];
__device__ __align__(16) bf16 g_xl [B_*CM*LL];
__device__ __align__(16) bf16 g_yh [B_*CM*LL];
__device__ __align__(16) bf16 g_yl [B_*CM*LL];
__device__ __align__(16) bf16 g_fh [B_*CM*LL];
__device__ __align__(16) bf16 g_fl [B_*CM*LL];
__device__ __align__(16) bf16 g_vh [B_*CM*LL];
__device__ __align__(16) bf16 g_vl [B_*CM*LL];
__device__ __align__(16) bf16 g_xmh[B_*DI*LL];
__device__ __align__(16) bf16 g_xml[B_*DI*LL];
__device__ __align__(16) bf16 g_ysh[B_*DI*LL];
__device__ __align__(16) bf16 g_ysl[B_*DI*LL];

// ---- bf16 hi/lo weights ----
__device__ __align__(16) bf16 g_Wq_h [CM*CM],        g_Wq_l [CM*CM];
__device__ __align__(16) bf16 g_Wkv_h[2*CM*CM],      g_Wkv_l[2*CM*CM];
__device__ __align__(16) bf16 g_Win_h[2*DI*CM],      g_Win_l[2*DI*CM];
__device__ __align__(16) bf16 g_Wxp_h[XDP*DI],       g_Wxp_l[XDP*DI];
__device__ __align__(16) bf16 g_Wfo_h[CM*(DI+CM)],   g_Wfo_l[CM*(DI+CM)];

// ---------------------------------------------------------------------------
// hi/lo split store helpers
// ---------------------------------------------------------------------------
__device__ __forceinline__ void store_hl4(bf16* __restrict__ ph, bf16* __restrict__ pl,
                                          float a, float b, float c, float d)
{
    bf16 h0 = __float2bfloat16(a), h1 = __float2bfloat16(b);
    bf16 h2 = __float2bfloat16(c), h3 = __float2bfloat16(d);
    __nv_bfloat162 hv0; hv0.x = h0; hv0.y = h1;
    __nv_bfloat162 hv1; hv1.x = h2; hv1.y = h3;
    *(__nv_bfloat162*)(ph)     = hv0;
    *(__nv_bfloat162*)(ph + 2) = hv1;
    __nv_bfloat162 lv0, lv1;
    lv0.x = __float2bfloat16(a - __bfloat162float(h0));
    lv0.y = __float2bfloat16(b - __bfloat162float(h1));
    lv1.x = __float2bfloat16(c - __bfloat162float(h2));
    lv1.y = __float2bfloat16(d - __bfloat162float(h3));
    *(__nv_bfloat162*)(pl)     = lv0;
    *(__nv_bfloat162*)(pl + 2) = lv1;
}

__global__ void cvt_hl_kernel(const float* __restrict__ src,
                              bf16* __restrict__ h, bf16* __restrict__ l, int n4)
{
    int i = blockIdx.x * blockDim.x + threadIdx.x;
    if (i >= n4) return;
    float4 v = ((const float4*)src)[i];
    store_hl4(h + i*4, l + i*4, v.x, v.y, v.z, v.w);
}

__global__ void cvt_w_kernel(const float* __restrict__ src,
                             bf16* __restrict__ h, bf16* __restrict__ l,
                             int rows, int cols, int rowsPad)
{
    int i = blockIdx.x * blockDim.x + threadIdx.x;
    if (i >= rowsPad*cols) return;
    int r = i / cols, c = i % cols;
    float v = (r < rows) ? src[r*cols + c] : 0.f;
    bf16 hh = __float2bfloat16(v);
    h[i] = hh;
    l[i] = __float2bfloat16(v - __bfloat162float(hh));
}

// ---------------------------------------------------------------------------
// Split-bf16 tensor-core GEMM: out[b,o,l] = sum_c W[o,c] * X[b,c,l]
// X = concat(x0[CIN0], x1[CIN1]) given as hi/lo bf16 pairs, channel-major.
// acc = Wh*Xh + Wh*Xl + Wl*Xh (fp32 accum)  -> ~2^-16 relative error.
// Block: 256 thr = 8 warps in 4(M) x 2(N); block tile 64(M) x 128(N).
// grid = (LL/128, B, COUTP/64)
// ---------------------------------------------------------------------------
template<int CIN0, int CIN1, int COUTP, int SPLIT>
__global__ __launch_bounds__(256) void mm_kernel(
    const bf16* __restrict__ x0h, const bf16* __restrict__ x0l,
    const bf16* __restrict__ x1h, const bf16* __restrict__ x1l,
    const bf16* __restrict__ wh,  const bf16* __restrict__ wl,
    float* __restrict__ out0, float* __restrict__ out1)
{
    constexpr int CIN = CIN0 + CIN1;
    const int warp = threadIdx.x >> 5;
    const int wm = warp >> 1, wn = warp & 1;
    const int b  = blockIdx.y;
    const int p0 = blockIdx.x * 128 + wn * 64;
    const int m0 = blockIdx.z * 64 + wm * 16;

    wmma::fragment<wmma::accumulator, 16, 16, 16, float> acc[4];
    #pragma unroll
    for (int f = 0; f < 4; ++f) wmma::fill_fragment(acc[f], 0.f);

    wmma::fragment<wmma::matrix_a, 16, 16, 16, bf16, wmma::row_major> ah, al;
    wmma::fragment<wmma::matrix_b, 16, 16, 16, bf16, wmma::row_major> bh, bl;

    for (int k0 = 0; k0 < CIN; k0 += 16) {
        wmma::load_matrix_sync(ah, wh + m0*CIN + k0, CIN);
        wmma::load_matrix_sync(al, wl + m0*CIN + k0, CIN);
        const bf16 *sh, *sl;
        if (CIN1 > 0 && k0 >= CIN0) {
            sh = x1h + (b*CIN1 + (k0 - CIN0))*LL + p0;
            sl = x1l + (b*CIN1 + (k0 - CIN0))*LL + p0;
        } else {
            sh = x0h + (b*CIN0 + k0)*LL + p0;
            sl = x0l + (b*CIN0 + k0)*LL + p0;
        }
        #pragma unroll
        for (int f = 0; f < 4; ++f) {
            wmma::load_matrix_sync(bh, sh + f*16, LL);
            wmma::load_matrix_sync(bl, sl + f*16, LL);
            wmma::mma_sync(acc[f], ah, bh, acc[f]);
            wmma::mma_sync(acc[f], ah, bl, acc[f]);
            wmma::mma_sync(acc[f], al, bh, acc[f]);
        }
    }

    float* base;
    if (m0 < SPLIT) base = out0 + (b*SPLIT + m0)*LL;
    else            base = out1 + (b*(COUTP - SPLIT) + (m0 - SPLIT))*LL;
    #pragma unroll
    for (int f = 0; f < 4; ++f)
        wmma::store_matrix_sync(base + p0 + f*16, acc[f], LL, wmma::mem_row_major);
}

// ---------------------------------------------------------------------------
// 3x3 depthwise, 4 px/thread. fused = dw3(q)+dw3(k) -> hi/lo; v = dw3(v) -> hi/lo
// ---------------------------------------------------------------------------
__global__ __launch_bounds__(256) void dw3_fused_kernel(
    const float* __restrict__ wqdw, const float* __restrict__ wkvdw)
{
    int idx = blockIdx.x * blockDim.x + threadIdx.x;   // B*2CM*HH*(WW/4)
    if (idx >= B_*2*CM*HH*(WW/4)) return;
    const int q4 = idx % (WW/4);
    const int h  = (idx / (WW/4)) % HH;
    const int c  = (idx / (WW/4) / HH) % (2*CM);
    const int b  =  idx / (WW/4) / HH / (2*CM);
    const int w0 = q4 * 4;

    float acc[4] = {0.f, 0.f, 0.f, 0.f};
    {
        const float* base = g_kvpre + (b*2*CM + c)*LL;
        const float* wk   = wkvdw + c*9;
        #pragma unroll
        for (int i = 0; i < 3; ++i) {
            const int hh = h - 1 + i;
            if (hh < 0 || hh >= HH) continue;
            const float* row = base + hh*WW;
            float rv[6];
            #pragma unroll
            for (int k = 0; k < 6; ++k) {
                const int wc = w0 - 1 + k;
                rv[k] = (wc >= 0 && wc < WW) ? row[wc] : 0.f;
            }
            #pragma unroll
            for (int p = 0; p < 4; ++p)
                acc[p] += wk[i*3+0]*rv[p] + wk[i*3+1]*rv[p+1] + wk[i*3+2]*rv[p+2];
        }
    }
    const int l0 = h*WW + w0;
    if (c < CM) {
        const float* base = g_qpre + (b*CM + c)*LL;
        const float* wq   = wqdw + c*9;
        #pragma unroll
        for (int i = 0; i < 3; ++i) {
            const int hh = h - 1 + i;
            if (hh < 0 || hh >= HH) continue;
            const float* row = base + hh*WW;
            float rv[6];
            #pragma unroll
            for (int k = 0; k < 6; ++k) {
                const int wc = w0 - 1 + k;
                rv[k] = (wc >= 0 && wc < WW) ? row[wc] : 0.f;
            }
            #pragma unroll
            for (int p = 0; p < 4; ++p)
                acc[p] += wq[i*3+0]*rv[p] + wq[i*3+1]*rv[p+1] + wq[i*3+2]*rv[p+2];
        }
        const int off = (b*CM + c)*LL + l0;
        store_hl4(g_fh + off, g_fl + off, acc[0], acc[1], acc[2], acc[3]);
    } else {
        const int off = (b*CM + (c - CM))*LL + l0;
        store_hl4(g_vh + off, g_vl + off, acc[0], acc[1], acc[2], acc[3]);
    }
}

// ---------------------------------------------------------------------------
// Causal depthwise conv1d (D_CONV=4) + SiLU, 4 px/thread -> fp32 + hi/lo
// ---------------------------------------------------------------------------
__global__ void conv1d_silu_kernel(const float* __restrict__ wconv,
                                   const float* __restrict__ bconv)
{
    int idx = blockIdx.x * blockDim.x + threadIdx.x;   // B*DI*(LL/4)
    if (idx >= B_*DI*(LL/4)) return;
    const int l0 = (idx % (LL/4)) * 4;
    const int d  = (idx / (LL/4)) % DI;
    const int b  =  idx / (LL/4) / DI;
    const float* src = g_xmpre + (b*DI + d)*LL;
    const float bc = bconv[d];
    float wc[4];
    #pragma unroll
    for (int k = 0; k < 4; ++k) wc[k] = wconv[d*4 + k];

    float s[7];
    #pragma unroll
    for (int k = 0; k < 7; ++k) {
        const int t = l0 - 3 + k;
        s[k] = (t >= 0) ? src[t] : 0.f;
    }
    float o[4];
    #pragma unroll
    for (int p = 0; p < 4; ++p) {
        float a = bc + wc[0]*s[p] + wc[1]*s[p+1] + wc[2]*s[p+2] + wc[3]*s[p+3];
        o[p] = a * (1.f / (1.f + __expf(-a)));
    }
    const int off = (b*DI + d)*LL + l0;
    *(float4*)&g_xm[off] = make_float4(o[0], o[1], o[2], o[3]);
    store_hl4(g_xmh + off, g_xml + off, o[0], o[1], o[2], o[3]);
}

// ---------------------------------------------------------------------------
// dt = softplus(xdbl[:,:8] @ w_dt.T + b_dt);  Bm/Cm slices  (xdbl stride = XDP)
// ---------------------------------------------------------------------------
__global__ __launch_bounds__(256) void dtbc_kernel(const float* __restrict__ wdt,
                                                   const float* __restrict__ bdt)
{
    __shared__ float ws[DI*DR];
    __shared__ float bs[DI];
    for (int i = threadIdx.x; i < DI*DR; i += 256) ws[i] = wdt[i];
    for (int i = threadIdx.x; i < DI;    i += 256) bs[i] = bdt[i];
    __syncthreads();

    int idx = blockIdx.x * 256 + threadIdx.x;
    if (idx >= B_*LL) return;
    const int l = idx % LL, b = idx / LL;

    float xr[DR];
    #pragma unroll
    for (int r = 0; r < DR; ++r) xr[r] = g_xdbl[(b*XDP + r)*LL + l];

    for (int j = 0; j < DI; ++j) {
        float s = bs[j];
        #pragma unroll
        for (int r = 0; r < DR; ++r) s += ws[j*DR + r] * xr[r];
        float dtv = (s > 20.f) ? s : log1pf(__expf(s));
        g_dt[(b*DI + j)*LL + l] = dtv;
    }
    #pragma unroll
    for (int i = 0; i < DS; ++i)
        g_Bm[(b*LL + l)*DS + i] = g_xdbl[(b*XDP + 8 + i)*LL + l];
    #pragma unroll
    for (int i = 0; i < DS; ++i)
        g_Cm[(b*LL + l)*DS + i] = g_xdbl[(b*XDP + 24 + i)*LL + l];
}

// ---------------------------------------------------------------------------
// Chunked selective scan (3 phases)
// ---------------------------------------------------------------------------
__global__ void scanA_kernel(const float* __restrict__ A_log)
{
    int tid = blockIdx.x * blockDim.x + threadIdx.x;
    if (tid >= B_*DI*NSEG*DS) return;
    const int n = tid & 15;
    const int g = tid >> 4;
    const int s = g % NSEG;
    const int d = (g / NSEG) % DI;
    const int b = g / (NSEG*DI);

    const float An = -__expf(A_log[d*DS + n]);
    const float* dtp = g_dt + (b*DI + d)*LL + s*SEG;
    const float* xmp = g_xm + (b*DI + d)*LL + s*SEG;
    const float* Bp  = g_Bm + (b*LL + s*SEG)*DS + n;

    float h = 0.f, sdt = 0.f;
    #pragma unroll 4
    for (int t = 0; t < SEG; ++t) {
        float dtv = dtp[t];
        float a   = __expf(An * dtv);
        h = a*h + dtv * xmp[t] * Bp[t*DS];
        sdt += dtv;
    }
    g_hend[g*DS + n] = h;
    if (n == 0) g_sumdt[g] = sdt;
}

__global__ void scanB_kernel(const float* __restrict__ A_log)
{
    int tid = blockIdx.x * blockDim.x + threadIdx.x;
    if (tid >= B_*DI*DS) return;
    const int n  = tid & 15;
    const int bd = tid >> 4;
    const int d  = bd % DI;
    const float An = -__expf(A_log[d*DS + n]);
    const int base = bd * NSEG;

    float h = 0.f;
    for (int s = 0; s < NSEG; ++s) {
        g_h0[(base + s)*DS + n] = h;
        float aseg = __expf(An * g_sumdt[base + s]);
        h = aseg*h + g_hend[(base + s)*DS + n];
    }
}

__global__ void scanC_kernel(const float* __restrict__ A_log,
                             const float* __restrict__ D_skip)
{
    int tid = blockIdx.x * blockDim.x + threadIdx.x;
    if (tid >= B_*DI*NSEG*DS) return;
    const int n = tid & 15;
    const int g = tid >> 4;
    const int s = g % NSEG;
    const int d = (g / NSEG) % DI;
    const int b = g / (NSEG*DI);

    const float An = -__expf(A_log[d*DS + n]);
    const float Dv = D_skip[d];
    const int cb = (b*DI + d)*LL + s*SEG;
    const float* dtp = g_dt + cb;
    const float* xmp = g_xm + cb;
    const float* zp  = g_z  + cb;
    const float* Bp  = g_Bm + (b*LL + s*SEG)*DS + n;
    const float* Cp  = g_Cm + (b*LL + s*SEG)*DS + n;

    float h = g_h0[g*DS + n];
    for (int t0 = 0; t0 < SEG; t0 += 4) {
        float yv[4];
        #pragma unroll
        for (int u = 0; u < 4; ++u) {
            const int t = t0 + u;
            float dtv = dtp[t];
            float xv  = xmp[t];
            float a   = __expf(An * dtv);
            h = a*h + dtv * xv * Bp[t*DS];
            float p = h * Cp[t*DS];
            p += __shfl_xor_sync(0xffffffffu, p, 1, 16);
            p += __shfl_xor_sync(0xffffffffu, p, 2, 16);
            p += __shfl_xor_sync(0xffffffffu, p, 4, 16);
            p += __shfl_xor_sync(0xffffffffu, p, 8, 16);
            float zv  = zp[t];
            float sig = 1.f / (1.f + __expf(-zv));
            yv[u] = (p + xv * Dv) * (zv * sig);
        }
        if (n == 0)
            store_hl4(g_ysh + cb + t0, g_ysl + cb + t0, yv[0], yv[1], yv[2], yv[3]);
    }
}

// ---------------------------------------------------------------------------
// Fold output projections: Wf = [ w_outproj @ w_out | w_outproj ]  (128 x 384)
// ---------------------------------------------------------------------------
__global__ void wf_kernel(const float* __restrict__ w_out,
                          const float* __restrict__ w_outproj)
{
    int idx = blockIdx.x * blockDim.x + threadIdx.x;
    if (idx >= CM*(DI+CM)) return;
    const int j = idx % (DI+CM);
    const int o = idx / (DI+CM);
    if (j < DI) {
        float acc = 0.f;
        for (int c = 0; c < CM; ++c)
            acc += w_outproj[o*CM + c] * w_out[c*DI + j];
        g_Wf[idx] = acc;
    } else {
        g_Wf[idx] = w_outproj[o*CM + (j - DI)];
    }
}

// ---------------------------------------------------------------------------
extern "C" void kernel_launch(void* const* d_in, const int* in_sizes, int n_in,
                              void* d_out, int out_size)
{
    (void)in_sizes; (void)n_in; (void)out_size;
    const float* x        = (const float*)d_in[0];
    const float* y        = (const float*)d_in[1];
    const float* w_q      = (const float*)d_in[2];
    const float* w_q_dw   = (const float*)d_in[3];
    const float* w_kv     = (const float*)d_in[4];
    const float* w_kv_dw  = (const float*)d_in[5];
    const float* w_in     = (const float*)d_in[6];
    const float* w_conv   = (const float*)d_in[7];
    const float* b_conv   = (const float*)d_in[8];
    const float* w_xproj  = (const float*)d_in[9];
    const float* w_dt     = (const float*)d_in[10];
    const float* b_dt     = (const float*)d_in[11];
    const float* A_log    = (const float*)d_in[12];
    const float* D_skip   = (const float*)d_in[13];
    const float* w_out    = (const float*)d_in[14];
    const float* w_outproj= (const float*)d_in[15];
    float* out = (float*)d_out;

    float *qpre, *kvpre, *xmpre, *zz, *xdbl, *Wf;
    bf16 *xh,*xl,*yh,*yl,*fh,*fl,*vh,*vl,*xmh,*xml,*ysh,*ysl;
    bf16 *Wqh,*Wql,*Wkvh,*Wkvl,*Winh,*Winl,*Wxph,*Wxpl,*Wfh,*Wfl;
    cudaGetSymbolAddress((void**)&qpre,  g_qpre);
    cudaGetSymbolAddress((void**)&kvpre, g_kvpre);
    cudaGetSymbolAddress((void**)&xmpre, g_xmpre);
    cudaGetSymbolAddress((void**)&zz,    g_z);
    cudaGetSymbolAddress((void**)&xdbl,  g_xdbl);
    cudaGetSymbolAddress((void**)&Wf,    g_Wf);
    cudaGetSymbolAddress((void**)&xh,  g_xh);  cudaGetSymbolAddress((void**)&xl,  g_xl);
    cudaGetSymbolAddress((void**)&yh,  g_yh);  cudaGetSymbolAddress((void**)&yl,  g_yl);
    cudaGetSymbolAddress((void**)&fh,  g_fh);  cudaGetSymbolAddress((void**)&fl,  g_fl);
    cudaGetSymbolAddress((void**)&vh,  g_vh);  cudaGetSymbolAddress((void**)&vl,  g_vl);
    cudaGetSymbolAddress((void**)&xmh, g_xmh); cudaGetSymbolAddress((void**)&xml, g_xml);
    cudaGetSymbolAddress((void**)&ysh, g_ysh); cudaGetSymbolAddress((void**)&ysl, g_ysl);
    cudaGetSymbolAddress((void**)&Wqh, g_Wq_h);  cudaGetSymbolAddress((void**)&Wql, g_Wq_l);
    cudaGetSymbolAddress((void**)&Wkvh,g_Wkv_h); cudaGetSymbolAddress((void**)&Wkvl,g_Wkv_l);
    cudaGetSymbolAddress((void**)&Winh,g_Win_h); cudaGetSymbolAddress((void**)&Winl,g_Win_l);
    cudaGetSymbolAddress((void**)&Wxph,g_Wxp_h); cudaGetSymbolAddress((void**)&Wxpl,g_Wxp_l);
    cudaGetSymbolAddress((void**)&Wfh, g_Wfo_h); cudaGetSymbolAddress((void**)&Wfl, g_Wfo_l);

    // --- weight prep ---
    wf_kernel<<<(CM*(DI+CM)+255)/256, 256>>>(w_out, w_outproj);
    cvt_w_kernel<<<(CM*CM+255)/256, 256>>>(w_q, Wqh, Wql, CM, CM, CM);
    cvt_w_kernel<<<(2*CM*CM+255)/256, 256>>>(w_kv, Wkvh, Wkvl, 2*CM, CM, 2*CM);
    cvt_w_kernel<<<(2*DI*CM+255)/256, 256>>>(w_in, Winh, Winl, 2*DI, CM, 2*DI);
    cvt_w_kernel<<<(XDP*DI+255)/256, 256>>>(w_xproj, Wxph, Wxpl, DR+2*DS, DI, XDP);
    cvt_w_kernel<<<(CM*(DI+CM)+255)/256, 256>>>(Wf, Wfh, Wfl, CM, DI+CM, CM);

    // --- input conversion ---
    cvt_hl_kernel<<<(B_*CM*LL/4+255)/256, 256>>>(x, xh, xl, B_*CM*LL/4);
    cvt_hl_kernel<<<(B_*CM*LL/4+255)/256, 256>>>(y, yh, yl, B_*CM*LL/4);

    // --- q = x @ w_q ; kv = y @ w_kv ---
    mm_kernel<128,0,128,128><<<dim3(72,B_,2),256>>>(xh,xl,xh,xl,Wqh,Wql,qpre,qpre);
    mm_kernel<128,0,256,256><<<dim3(72,B_,4),256>>>(yh,yl,yh,yl,Wkvh,Wkvl,kvpre,kvpre);

    // --- depthwise 3x3 + fuse q+k, extract v (emits hi/lo) ---
    dw3_fused_kernel<<<(B_*2*CM*HH*(WW/4)+255)/256, 256>>>(w_q_dw, w_kv_dw);

    // --- xz = fused @ w_in.T -> xmpre(256) + z(256) ---
    mm_kernel<128,0,512,256><<<dim3(72,B_,8),256>>>(fh,fl,fh,fl,Winh,Winl,xmpre,zz);

    // --- causal conv1d + silu (fp32 + hi/lo) ---
    conv1d_silu_kernel<<<(B_*DI*(LL/4)+255)/256, 256>>>(w_conv, b_conv);

    // --- xdbl = xm @ w_xproj.T (256 -> 40, padded 64) ---
    mm_kernel<256,0,XDP,XDP><<<dim3(72,B_,1),256>>>(xmh,xml,xmh,xml,Wxph,Wxpl,xdbl,xdbl);

    // --- dt / B / C ---
    dtbc_kernel<<<(B_*LL)/256, 256>>>(w_dt, b_dt);

    // --- chunked selective scan ---
    scanA_kernel<<<(B_*DI*NSEG*DS)/256, 256>>>(A_log);
    scanB_kernel<<<(B_*DI*DS)/256, 256>>>(A_log);
    scanC_kernel<<<(B_*DI*NSEG*DS)/256, 256>>>(A_log, D_skip);

    // --- out = [ys ; v] @ Wf.T ---
    mm_kernel<256,128,128,128><<<dim3(72,B_,2),256>>>(ysh,ysl,vh,vl,Wfh,Wfl,out,out);
}

// round 17
// speedup vs baseline: 1.3270x; 1.3270x over previous
#include <cuda_runtime.h>
#include <cuda_bf16.h>
#include <mma.h>
#include <math.h>
#include <stdint.h>

using namespace nvcuda;

// ---------------------------------------------------------------------------
// CrossMambaBlock — split-bf16 tensor-core GEMMs (smem-staged) + fp32 scan
// B=2, D_MODEL=128, H=W=96 (L=9216), D_INNER=256, D_STATE=16, D_CONV=4, DT_RANK=8
// ---------------------------------------------------------------------------

#define B_    2
#define CM    128
#define HH    96
#define WW    96
#define LL    (HH*WW)        // 9216
#define DI    256
#define DS    16
#define DR    8
#define NSEG  32
#define SEG   (LL/NSEG)      // 288
#define XDP   64             // padded xdbl channel count (real = 40)

typedef __nv_bfloat16 bf16;

// ---- fp32 scratch ----
__device__ __align__(16) float g_qpre [B_*CM*LL];
__device__ __align__(16) float g_kvpre[B_*2*CM*LL];
__device__ __align__(16) float g_xmpre[B_*DI*LL];
__device__ __align__(16) float g_z    [B_*DI*LL];
__device__ __align__(16) float g_xm   [B_*DI*LL];
__device__ __align__(16) float g_xdbl [B_*XDP*LL];
__device__ __align__(16) float g_dt   [B_*DI*LL];
__device__ __align__(16) float g_Bm   [B_*LL*DS];
__device__ __align__(16) float g_Cm   [B_*LL*DS];
__device__ __align__(16) float g_hend [B_*DI*NSEG*DS];
__device__ __align__(16) float g_h0   [B_*DI*NSEG*DS];
__device__ __align__(16) float g_sumdt[B_*DI*NSEG];
__device__ __align__(16) float g_Wf   [CM*(DI+CM)];

// ---- bf16 hi/lo activation scratch ----
__device__ __align__(16) bf16 g_xh [B_*CM*LL];
__device__ __align__(16) bf16 g_xl [B_*CM*LL];
__device__ __align__(16) bf16 g_yh [B_*CM*LL];
__device__ __align__(16) bf16 g_yl [B_*CM*LL];
__device__ __align__(16) bf16 g_fh [B_*CM*LL];
__device__ __align__(16) bf16 g_fl [B_*CM*LL];
__device__ __align__(16) bf16 g_vh [B_*CM*LL];
__device__ __align__(16) bf16 g_vl [B_*CM*LL];
__device__ __align__(16) bf16 g_xmh[B_*DI*LL];
__device__ __align__(16) bf16 g_xml[B_*DI*LL];
__device__ __align__(16) bf16 g_ysh[B_*DI*LL];
__device__ __align__(16) bf16 g_ysl[B_*DI*LL];

// ---- bf16 hi/lo weights ----
__device__ __align__(16) bf16 g_Wq_h [CM*CM],        g_Wq_l [CM*CM];
__device__ __align__(16) bf16 g_Wkv_h[2*CM*CM],      g_Wkv_l[2*CM*CM];
__device__ __align__(16) bf16 g_Win_h[2*DI*CM],      g_Win_l[2*DI*CM];
__device__ __align__(16) bf16 g_Wxp_h[XDP*DI],       g_Wxp_l[XDP*DI];
__device__ __align__(16) bf16 g_Wfo_h[CM*(DI+CM)],   g_Wfo_l[CM*(DI+CM)];

// ---------------------------------------------------------------------------
// hi/lo split store helpers
// ---------------------------------------------------------------------------
__device__ __forceinline__ void store_hl4(bf16* __restrict__ ph, bf16* __restrict__ pl,
                                          float a, float b, float c, float d)
{
    bf16 h0 = __float2bfloat16(a), h1 = __float2bfloat16(b);
    bf16 h2 = __float2bfloat16(c), h3 = __float2bfloat16(d);
    __nv_bfloat162 hv0; hv0.x = h0; hv0.y = h1;
    __nv_bfloat162 hv1; hv1.x = h2; hv1.y = h3;
    *(__nv_bfloat162*)(ph)     = hv0;
    *(__nv_bfloat162*)(ph + 2) = hv1;
    __nv_bfloat162 lv0, lv1;
    lv0.x = __float2bfloat16(a - __bfloat162float(h0));
    lv0.y = __float2bfloat16(b - __bfloat162float(h1));
    lv1.x = __float2bfloat16(c - __bfloat162float(h2));
    lv1.y = __float2bfloat16(d - __bfloat162float(h3));
    *(__nv_bfloat162*)(pl)     = lv0;
    *(__nv_bfloat162*)(pl + 2) = lv1;
}

__global__ void cvt_hl_kernel(const float* __restrict__ src,
                              bf16* __restrict__ h, bf16* __restrict__ l, int n4)
{
    int i = blockIdx.x * blockDim.x + threadIdx.x;
    if (i >= n4) return;
    float4 v = ((const float4*)src)[i];
    store_hl4(h + i*4, l + i*4, v.x, v.y, v.z, v.w);
}

__global__ void cvt_w_kernel(const float* __restrict__ src,
                             bf16* __restrict__ h, bf16* __restrict__ l,
                             int rows, int cols, int rowsPad)
{
    int i = blockIdx.x * blockDim.x + threadIdx.x;
    if (i >= rowsPad*cols) return;
    int r = i / cols, c = i % cols;
    float v = (r < rows) ? src[r*cols + c] : 0.f;
    bf16 hh = __float2bfloat16(v);
    h[i] = hh;
    l[i] = __float2bfloat16(v - __bfloat162float(hh));
}

// ---------------------------------------------------------------------------
// Split-bf16 tensor-core GEMM, smem-staged:
//   out[b,o,l] = sum_c W[o,c] * X[b,c,l]
// X = concat(x0[CIN0], x1[CIN1]) hi/lo bf16, channel-major (rows contiguous in l).
// acc = Wh*Xh + Wh*Xl + Wl*Xh (fp32 accum).
// Block = 256 thr = 8 warps (4M x 2N); tile 64(M) x 128(N), K-chunk 32.
// grid = (LL/128, B, COUTP/64)
// ---------------------------------------------------------------------------
#define KT   32
#define WLD  (KT+8)     // 40 elems = 80B stride (16B multiple)
#define XLD  136        // 272B stride (16B multiple)

template<int CIN0, int CIN1, int COUTP, int SPLIT>
__global__ __launch_bounds__(256) void mm_kernel(
    const bf16* __restrict__ x0h, const bf16* __restrict__ x0l,
    const bf16* __restrict__ x1h, const bf16* __restrict__ x1l,
    const bf16* __restrict__ wh,  const bf16* __restrict__ wl,
    float* __restrict__ out0, float* __restrict__ out1)
{
    constexpr int CIN = CIN0 + CIN1;
    __shared__ bf16 sWh[64*WLD], sWl[64*WLD];
    __shared__ bf16 sXh[KT*XLD], sXl[KT*XLD];

    const int tid  = threadIdx.x;
    const int warp = tid >> 5;
    const int wm = warp >> 1, wn = warp & 1;
    const int b  = blockIdx.y;
    const int p0 = blockIdx.x * 128;
    const int m0 = blockIdx.z * 64;

    wmma::fragment<wmma::accumulator, 16, 16, 16, float> acc[4];
    #pragma unroll
    for (int f = 0; f < 4; ++f) wmma::fill_fragment(acc[f], 0.f);

    wmma::fragment<wmma::matrix_a, 16, 16, 16, bf16, wmma::row_major> ah, al;
    wmma::fragment<wmma::matrix_b, 16, 16, 16, bf16, wmma::row_major> bh, bl;

    for (int k0 = 0; k0 < CIN; k0 += KT) {
        // --- load W tile 64x32 (hi+lo): 8 bf16 (16B) per thread each ---
        {
            const int r  = tid >> 2;          // 0..63
            const int cs = (tid & 3) * 8;     // 0,8,16,24
            const int gofs = (m0 + r)*CIN + k0 + cs;
            *(uint4*)&sWh[r*WLD + cs] = *(const uint4*)&wh[gofs];
            *(uint4*)&sWl[r*WLD + cs] = *(const uint4*)&wl[gofs];
        }
        // --- load X tile 32x128 (hi+lo): 16 bf16 per thread each ---
        {
            const int r  = tid >> 3;          // 0..31  (channel k0+r)
            const int cs = (tid & 7) * 16;    // 0..112
            const int c  = k0 + r;
            const bf16 *sh, *sl;
            if (CIN1 > 0 && c >= CIN0) {
                sh = x1h + (b*CIN1 + (c - CIN0))*LL + p0;
                sl = x1l + (b*CIN1 + (c - CIN0))*LL + p0;
            } else {
                sh = x0h + (b*CIN0 + c)*LL + p0;
                sl = x0l + (b*CIN0 + c)*LL + p0;
            }
            *(uint4*)&sXh[r*XLD + cs]     = *(const uint4*)&sh[cs];
            *(uint4*)&sXh[r*XLD + cs + 8] = *(const uint4*)&sh[cs + 8];
            *(uint4*)&sXl[r*XLD + cs]     = *(const uint4*)&sl[cs];
            *(uint4*)&sXl[r*XLD + cs + 8] = *(const uint4*)&sl[cs + 8];
        }
        __syncthreads();

        #pragma unroll
        for (int ks = 0; ks < KT; ks += 16) {
            wmma::load_matrix_sync(ah, &sWh[(wm*16)*WLD + ks], WLD);
            wmma::load_matrix_sync(al, &sWl[(wm*16)*WLD + ks], WLD);
            #pragma unroll
            for (int f = 0; f < 4; ++f) {
                const int nn = wn*64 + f*16;
                wmma::load_matrix_sync(bh, &sXh[ks*XLD + nn], XLD);
                wmma::load_matrix_sync(bl, &sXl[ks*XLD + nn], XLD);
                wmma::mma_sync(acc[f], ah, bh, acc[f]);
                wmma::mma_sync(acc[f], ah, bl, acc[f]);
                wmma::mma_sync(acc[f], al, bh, acc[f]);
            }
        }
        __syncthreads();
    }

    const int mrow = m0 + wm*16;
    float* base;
    if (mrow < SPLIT) base = out0 + (b*SPLIT + mrow)*LL;
    else              base = out1 + (b*(COUTP - SPLIT) + (mrow - SPLIT))*LL;
    #pragma unroll
    for (int f = 0; f < 4; ++f)
        wmma::store_matrix_sync(base + p0 + wn*64 + f*16, acc[f], LL, wmma::mem_row_major);
}

// ---------------------------------------------------------------------------
// 3x3 depthwise, 4 px/thread. fused = dw3(q)+dw3(k) -> hi/lo; v = dw3(v) -> hi/lo
// ---------------------------------------------------------------------------
__global__ __launch_bounds__(256) void dw3_fused_kernel(
    const float* __restrict__ wqdw, const float* __restrict__ wkvdw)
{
    int idx = blockIdx.x * blockDim.x + threadIdx.x;   // B*2CM*HH*(WW/4)
    if (idx >= B_*2*CM*HH*(WW/4)) return;
    const int q4 = idx % (WW/4);
    const int h  = (idx / (WW/4)) % HH;
    const int c  = (idx / (WW/4) / HH) % (2*CM);
    const int b  =  idx / (WW/4) / HH / (2*CM);
    const int w0 = q4 * 4;

    float acc[4] = {0.f, 0.f, 0.f, 0.f};
    {
        const float* base = g_kvpre + (b*2*CM + c)*LL;
        const float* wk   = wkvdw + c*9;
        #pragma unroll
        for (int i = 0; i < 3; ++i) {
            const int hh = h - 1 + i;
            if (hh < 0 || hh >= HH) continue;
            const float* row = base + hh*WW;
            float rv[6];
            #pragma unroll
            for (int k = 0; k < 6; ++k) {
                const int wc = w0 - 1 + k;
                rv[k] = (wc >= 0 && wc < WW) ? row[wc] : 0.f;
            }
            #pragma unroll
            for (int p = 0; p < 4; ++p)
                acc[p] += wk[i*3+0]*rv[p] + wk[i*3+1]*rv[p+1] + wk[i*3+2]*rv[p+2];
        }
    }
    const int l0 = h*WW + w0;
    if (c < CM) {
        const float* base = g_qpre + (b*CM + c)*LL;
        const float* wq   = wqdw + c*9;
        #pragma unroll
        for (int i = 0; i < 3; ++i) {
            const int hh = h - 1 + i;
            if (hh < 0 || hh >= HH) continue;
            const float* row = base + hh*WW;
            float rv[6];
            #pragma unroll
            for (int k = 0; k < 6; ++k) {
                const int wc = w0 - 1 + k;
                rv[k] = (wc >= 0 && wc < WW) ? row[wc] : 0.f;
            }
            #pragma unroll
            for (int p = 0; p < 4; ++p)
                acc[p] += wq[i*3+0]*rv[p] + wq[i*3+1]*rv[p+1] + wq[i*3+2]*rv[p+2];
        }
        const int off = (b*CM + c)*LL + l0;
        store_hl4(g_fh + off, g_fl + off, acc[0], acc[1], acc[2], acc[3]);
    } else {
        const int off = (b*CM + (c - CM))*LL + l0;
        store_hl4(g_vh + off, g_vl + off, acc[0], acc[1], acc[2], acc[3]);
    }
}

// ---------------------------------------------------------------------------
// Causal depthwise conv1d (D_CONV=4) + SiLU, 4 px/thread -> fp32 + hi/lo
// ---------------------------------------------------------------------------
__global__ void conv1d_silu_kernel(const float* __restrict__ wconv,
                                   const float* __restrict__ bconv)
{
    int idx = blockIdx.x * blockDim.x + threadIdx.x;   // B*DI*(LL/4)
    if (idx >= B_*DI*(LL/4)) return;
    const int l0 = (idx % (LL/4)) * 4;
    const int d  = (idx / (LL/4)) % DI;
    const int b  =  idx / (LL/4) / DI;
    const float* src = g_xmpre + (b*DI + d)*LL;
    const float bc = bconv[d];
    float wc[4];
    #pragma unroll
    for (int k = 0; k < 4; ++k) wc[k] = wconv[d*4 + k];

    float s[7];
    #pragma unroll
    for (int k = 0; k < 7; ++k) {
        const int t = l0 - 3 + k;
        s[k] = (t >= 0) ? src[t] : 0.f;
    }
    float o[4];
    #pragma unroll
    for (int p = 0; p < 4; ++p) {
        float a = bc + wc[0]*s[p] + wc[1]*s[p+1] + wc[2]*s[p+2] + wc[3]*s[p+3];
        o[p] = a * (1.f / (1.f + __expf(-a)));
    }
    const int off = (b*DI + d)*LL + l0;
    *(float4*)&g_xm[off] = make_float4(o[0], o[1], o[2], o[3]);
    store_hl4(g_xmh + off, g_xml + off, o[0], o[1], o[2], o[3]);
}

// ---------------------------------------------------------------------------
// dt = softplus(xdbl[:,:8] @ w_dt.T + b_dt);  Bm/Cm slices  (xdbl stride = XDP)
// ---------------------------------------------------------------------------
__global__ __launch_bounds__(256) void dtbc_kernel(const float* __restrict__ wdt,
                                                   const float* __restrict__ bdt)
{
    __shared__ float ws[DI*DR];
    __shared__ float bs[DI];
    for (int i = threadIdx.x; i < DI*DR; i += 256) ws[i] = wdt[i];
    for (int i = threadIdx.x; i < DI;    i += 256) bs[i] = bdt[i];
    __syncthreads();

    int idx = blockIdx.x * 256 + threadIdx.x;
    if (idx >= B_*LL) return;
    const int l = idx % LL, b = idx / LL;

    float xr[DR];
    #pragma unroll
    for (int r = 0; r < DR; ++r) xr[r] = g_xdbl[(b*XDP + r)*LL + l];

    for (int j = 0; j < DI; ++j) {
        float s = bs[j];
        #pragma unroll
        for (int r = 0; r < DR; ++r) s += ws[j*DR + r] * xr[r];
        float dtv = (s > 20.f) ? s : log1pf(__expf(s));
        g_dt[(b*DI + j)*LL + l] = dtv;
    }
    #pragma unroll
    for (int i = 0; i < DS; ++i)
        g_Bm[(b*LL + l)*DS + i] = g_xdbl[(b*XDP + 8 + i)*LL + l];
    #pragma unroll
    for (int i = 0; i < DS; ++i)
        g_Cm[(b*LL + l)*DS + i] = g_xdbl[(b*XDP + 24 + i)*LL + l];
}

// ---------------------------------------------------------------------------
// Chunked selective scan (3 phases)
// ---------------------------------------------------------------------------
__global__ void scanA_kernel(const float* __restrict__ A_log)
{
    int tid = blockIdx.x * blockDim.x + threadIdx.x;
    if (tid >= B_*DI*NSEG*DS) return;
    const int n = tid & 15;
    const int g = tid >> 4;
    const int s = g % NSEG;
    const int d = (g / NSEG) % DI;
    const int b = g / (NSEG*DI);

    const float An = -__expf(A_log[d*DS + n]);
    const float* dtp = g_dt + (b*DI + d)*LL + s*SEG;
    const float* xmp = g_xm + (b*DI + d)*LL + s*SEG;
    const float* Bp  = g_Bm + (b*LL + s*SEG)*DS + n;

    float h = 0.f, sdt = 0.f;
    #pragma unroll 4
    for (int t = 0; t < SEG; ++t) {
        float dtv = dtp[t];
        float a   = __expf(An * dtv);
        h = a*h + dtv * xmp[t] * Bp[t*DS];
        sdt += dtv;
    }
    g_hend[g*DS + n] = h;
    if (n == 0) g_sumdt[g] = sdt;
}

__global__ void scanB_kernel(const float* __restrict__ A_log)
{
    int tid = blockIdx.x * blockDim.x + threadIdx.x;
    if (tid >= B_*DI*DS) return;
    const int n  = tid & 15;
    const int bd = tid >> 4;
    const int d  = bd % DI;
    const float An = -__expf(A_log[d*DS + n]);
    const int base = bd * NSEG;

    float h = 0.f;
    for (int s = 0; s < NSEG; ++s) {
        g_h0[(base + s)*DS + n] = h;
        float aseg = __expf(An * g_sumdt[base + s]);
        h = aseg*h + g_hend[(base + s)*DS + n];
    }
}

__global__ void scanC_kernel(const float* __restrict__ A_log,
                             const float* __restrict__ D_skip)
{
    int tid = blockIdx.x * blockDim.x + threadIdx.x;
    if (tid >= B_*DI*NSEG*DS) return;
    const int n = tid & 15;
    const int g = tid >> 4;
    const int s = g % NSEG;
    const int d = (g / NSEG) % DI;
    const int b = g / (NSEG*DI);

    const float An = -__expf(A_log[d*DS + n]);
    const float Dv = D_skip[d];
    const int cb = (b*DI + d)*LL + s*SEG;
    const float* dtp = g_dt + cb;
    const float* xmp = g_xm + cb;
    const float* zp  = g_z  + cb;
    const float* Bp  = g_Bm + (b*LL + s*SEG)*DS + n;
    const float* Cp  = g_Cm + (b*LL + s*SEG)*DS + n;

    float h = g_h0[g*DS + n];
    for (int t0 = 0; t0 < SEG; t0 += 4) {
        float yv[4];
        #pragma unroll
        for (int u = 0; u < 4; ++u) {
            const int t = t0 + u;
            float dtv = dtp[t];
            float xv  = xmp[t];
            float a   = __expf(An * dtv);
            h = a*h + dtv * xv * Bp[t*DS];
            float p = h * Cp[t*DS];
            p += __shfl_xor_sync(0xffffffffu, p, 1, 16);
            p += __shfl_xor_sync(0xffffffffu, p, 2, 16);
            p += __shfl_xor_sync(0xffffffffu, p, 4, 16);
            p += __shfl_xor_sync(0xffffffffu, p, 8, 16);
            float zv  = zp[t];
            float sig = 1.f / (1.f + __expf(-zv));
            yv[u] = (p + xv * Dv) * (zv * sig);
        }
        if (n == 0)
            store_hl4(g_ysh + cb + t0, g_ysl + cb + t0, yv[0], yv[1], yv[2], yv[3]);
    }
}

// ---------------------------------------------------------------------------
// Fold output projections: Wf = [ w_outproj @ w_out | w_outproj ]  (128 x 384)
// ---------------------------------------------------------------------------
__global__ void wf_kernel(const float* __restrict__ w_out,
                          const float* __restrict__ w_outproj)
{
    int idx = blockIdx.x * blockDim.x + threadIdx.x;
    if (idx >= CM*(DI+CM)) return;
    const int j = idx % (DI+CM);
    const int o = idx / (DI+CM);
    if (j < DI) {
        float acc = 0.f;
        for (int c = 0; c < CM; ++c)
            acc += w_outproj[o*CM + c] * w_out[c*DI + j];
        g_Wf[idx] = acc;
    } else {
        g_Wf[idx] = w_outproj[o*CM + (j - DI)];
    }
}

// ---------------------------------------------------------------------------
extern "C" void kernel_launch(void* const* d_in, const int* in_sizes, int n_in,
                              void* d_out, int out_size)
{
    (void)in_sizes; (void)n_in; (void)out_size;
    const float* x        = (const float*)d_in[0];
    const float* y        = (const float*)d_in[1];
    const float* w_q      = (const float*)d_in[2];
    const float* w_q_dw   = (const float*)d_in[3];
    const float* w_kv     = (const float*)d_in[4];
    const float* w_kv_dw  = (const float*)d_in[5];
    const float* w_in     = (const float*)d_in[6];
    const float* w_conv   = (const float*)d_in[7];
    const float* b_conv   = (const float*)d_in[8];
    const float* w_xproj  = (const float*)d_in[9];
    const float* w_dt     = (const float*)d_in[10];
    const float* b_dt     = (const float*)d_in[11];
    const float* A_log    = (const float*)d_in[12];
    const float* D_skip   = (const float*)d_in[13];
    const float* w_out    = (const float*)d_in[14];
    const float* w_outproj= (const float*)d_in[15];
    float* out = (float*)d_out;

    float *qpre, *kvpre, *xmpre, *zz, *xdbl, *Wf;
    bf16 *xh,*xl,*yh,*yl,*fh,*fl,*vh,*vl,*xmh,*xml,*ysh,*ysl;
    bf16 *Wqh,*Wql,*Wkvh,*Wkvl,*Winh,*Winl,*Wxph,*Wxpl,*Wfh,*Wfl;
    cudaGetSymbolAddress((void**)&qpre,  g_qpre);
    cudaGetSymbolAddress((void**)&kvpre, g_kvpre);
    cudaGetSymbolAddress((void**)&xmpre, g_xmpre);
    cudaGetSymbolAddress((void**)&zz,    g_z);
    cudaGetSymbolAddress((void**)&xdbl,  g_xdbl);
    cudaGetSymbolAddress((void**)&Wf,    g_Wf);
    cudaGetSymbolAddress((void**)&xh,  g_xh);  cudaGetSymbolAddress((void**)&xl,  g_xl);
    cudaGetSymbolAddress((void**)&yh,  g_yh);  cudaGetSymbolAddress((void**)&yl,  g_yl);
    cudaGetSymbolAddress((void**)&fh,  g_fh);  cudaGetSymbolAddress((void**)&fl,  g_fl);
    cudaGetSymbolAddress((void**)&vh,  g_vh);  cudaGetSymbolAddress((void**)&vl,  g_vl);
    cudaGetSymbolAddress((void**)&xmh, g_xmh); cudaGetSymbolAddress((void**)&xml, g_xml);
    cudaGetSymbolAddress((void**)&ysh, g_ysh); cudaGetSymbolAddress((void**)&ysl, g_ysl);
    cudaGetSymbolAddress((void**)&Wqh, g_Wq_h);  cudaGetSymbolAddress((void**)&Wql, g_Wq_l);
    cudaGetSymbolAddress((void**)&Wkvh,g_Wkv_h); cudaGetSymbolAddress((void**)&Wkvl,g_Wkv_l);
    cudaGetSymbolAddress((void**)&Winh,g_Win_h); cudaGetSymbolAddress((void**)&Winl,g_Win_l);
    cudaGetSymbolAddress((void**)&Wxph,g_Wxp_h); cudaGetSymbolAddress((void**)&Wxpl,g_Wxp_l);
    cudaGetSymbolAddress((void**)&Wfh, g_Wfo_h); cudaGetSymbolAddress((void**)&Wfl, g_Wfo_l);

    // --- weight prep ---
    wf_kernel<<<(CM*(DI+CM)+255)/256, 256>>>(w_out, w_outproj);
    cvt_w_kernel<<<(CM*CM+255)/256, 256>>>(w_q, Wqh, Wql, CM, CM, CM);
    cvt_w_kernel<<<(2*CM*CM+255)/256, 256>>>(w_kv, Wkvh, Wkvl, 2*CM, CM, 2*CM);
    cvt_w_kernel<<<(2*DI*CM+255)/256, 256>>>(w_in, Winh, Winl, 2*DI, CM, 2*DI);
    cvt_w_kernel<<<(XDP*DI+255)/256, 256>>>(w_xproj, Wxph, Wxpl, DR+2*DS, DI, XDP);
    cvt_w_kernel<<<(CM*(DI+CM)+255)/256, 256>>>(Wf, Wfh, Wfl, CM, DI+CM, CM);

    // --- input conversion ---
    cvt_hl_kernel<<<(B_*CM*LL/4+255)/256, 256>>>(x, xh, xl, B_*CM*LL/4);
    cvt_hl_kernel<<<(B_*CM*LL/4+255)/256, 256>>>(y, yh, yl, B_*CM*LL/4);

    // --- q = x @ w_q ; kv = y @ w_kv ---
    mm_kernel<128,0,128,128><<<dim3(72,B_,2),256>>>(xh,xl,xh,xl,Wqh,Wql,qpre,qpre);
    mm_kernel<128,0,256,256><<<dim3(72,B_,4),256>>>(yh,yl,yh,yl,Wkvh,Wkvl,kvpre,kvpre);

    // --- depthwise 3x3 + fuse q+k, extract v (emits hi/lo) ---
    dw3_fused_kernel<<<(B_*2*CM*HH*(WW/4)+255)/256, 256>>>(w_q_dw, w_kv_dw);

    // --- xz = fused @ w_in.T -> xmpre(256) + z(256) ---
    mm_kernel<128,0,512,256><<<dim3(72,B_,8),256>>>(fh,fl,fh,fl,Winh,Winl,xmpre,zz);

    // --- causal conv1d + silu (fp32 + hi/lo) ---
    conv1d_silu_kernel<<<(B_*DI*(LL/4)+255)/256, 256>>>(w_conv, b_conv);

    // --- xdbl = xm @ w_xproj.T (256 -> 40, padded 64) ---
    mm_kernel<256,0,XDP,XDP><<<dim3(72,B_,1),256>>>(xmh,xml,xmh,xml,Wxph,Wxpl,xdbl,xdbl);

    // --- dt / B / C ---
    dtbc_kernel<<<(B_*LL)/256, 256>>>(w_dt, b_dt);

    // --- chunked selective scan ---
    scanA_kernel<<<(B_*DI*NSEG*DS)/256, 256>>>(A_log);
    scanB_kernel<<<(B_*DI*DS)/256, 256>>>(A_log);
    scanC_kernel<<<(B_*DI*NSEG*DS)/256, 256>>>(A_log, D_skip);

    // --- out = [ys ; v] @ Wf.T ---
    mm_kernel<256,128,128,128><<<dim3(72,B_,2),256>>>(ysh,ysl,vh,vl,Wfh,Wfl,out,out);
}